// round 6
// baseline (speedup 1.0000x reference)
#include <cuda_runtime.h>

#define M_TOT 64
#define HF 120
#define WF 160
#define C_IN 128
#define H_OUT 480
#define W_OUT 640
#define SZ_IMG (M_TOT * H_OUT * W_OUT)   // 19,660,800
#define N_EXP 13
#define WT2 4608                         // 9k*4cg*8cp*8o*2 floats per (unit,chunk)
#define ROI_PER 5184                     // 16*324 floats per (m,chunk)

typedef unsigned long long ull;

// Scratch (zero-initialized at load; padded slots stay zero forever).
__device__ __align__(16) float g_wT  [N_EXP * 6 * 8 * WT2];   // [lab][unit][chunk][k][cg][cp][o2]
__device__ __align__(16) float g_roiT[M_TOT * 8 * ROI_PER];   // [m][chunk][row16][x18][ci16+2]
__device__ __align__(16) float g_h1  [M_TOT * 64 * 16 * 16];  // padded conv_c1 output
__device__ float g_gap [M_TOT * C_IN];
__device__ float g_cpart[M_TOT * 8 * 196];
__device__ __align__(16) float g_rowh[M_TOT * 14 * 640];      // horiz-interp rows (+bias)
__device__ float g_ss  [M_TOT * 2];

__device__ __forceinline__ void unpack2(ull v, float& lo, float& hi) {
    asm("mov.b64 {%0, %1}, %2;" : "=f"(lo), "=f"(hi) : "l"(v));
}
__device__ __forceinline__ void ffma2(ull& d, ull a, ull b) {
    asm("fma.rn.f32x2 %0, %1, %2, %3;" : "=l"(d) : "l"(a), "l"(b), "l"(d));
}

// ---------------------------------------------------------------------------
// K1: fused weight transpose + ROI align. grid 1136: [0,624) wt, [624,1136) roi.
// ---------------------------------------------------------------------------
__global__ void k_prep(const float* __restrict__ w_s, const float* __restrict__ w_c1,
                       const float* __restrict__ fmap, const float* __restrict__ boxes)
{
    if (blockIdx.x < 624) {
        int id  = blockIdx.x;             // lab*48 + unit*8 + chunk
        int lab = id / 48, rem = id % 48;
        int unit = rem >> 3, chunk = rem & 7;
        const float* wb = (unit < 4)
            ? w_s  + ((size_t)lab*128 + unit*32)     * 1152
            : w_c1 + ((size_t)lab*64  + (unit-4)*32) * 1152;
        float* dst = g_wT + ((size_t)(lab*6 + unit)*8 + chunk) * WT2;
        for (int d = threadIdx.x; d < WT2; d += 256) {
            int k = d / 512, r2 = d % 512;
            int cg = r2 / 128, r3 = r2 % 128;
            int cp = r3 / 16, oe = r3 % 16;
            int o = oe >> 1, e = oe & 1;
            dst[d] = wb[(size_t)(cg*8 + o)*1152 + chunk*144 + (2*cp + e)*9 + k];
        }
        return;
    }

    int bi = blockIdx.x - 624;            // m*8 + seg
    int m = bi >> 3, seg = bi & 7;
    int b = m >> 4;
    __shared__ int   y0s[14], x0s[14];
    __shared__ float wys[14], wxs[14];

    float b0 = boxes[m*4+0], b1 = boxes[m*4+1], b2 = boxes[m*4+2], b3 = boxes[m*4+3];
    float y1 = 0.6f*b0, x1 = 0.6f*b1;
    float y2 = y1 + 0.1f + 0.3f*b2;
    float x2 = x1 + 0.1f + 0.3f*b3;

    int tid = threadIdx.x;
    if (tid < 14) {
        float t  = (tid + 0.5f) / 14.0f;
        float ys = (y1 + (y2 - y1) * t) * (float)(HF - 1);
        int y0 = (int)floorf(ys);
        if (y0 < 0) y0 = 0; if (y0 > HF-2) y0 = HF-2;
        y0s[tid] = y0;
        wys[tid] = fminf(fmaxf(ys - (float)y0, 0.f), 1.f);
    } else if (tid >= 32 && tid < 46) {
        int j = tid - 32;
        float t  = (j + 0.5f) / 14.0f;
        float xs = (x1 + (x2 - x1) * t) * (float)(WF - 1);
        int x0 = (int)floorf(xs);
        if (x0 < 0) x0 = 0; if (x0 > WF-2) x0 = WF-2;
        x0s[j] = x0;
        wxs[j] = fminf(fmaxf(xs - (float)x0, 0.f), 1.f);
    }
    __syncthreads();

    int base = seg * 16 * 196;
    for (int rel = tid; rel < 16 * 196; rel += 256) {
        int flat = base + rel;
        int c = flat / 196, r = flat % 196;
        int i = r / 14, j = r % 14;
        int y0 = y0s[i], x0 = x0s[j];
        float wy = wys[i], wx = wxs[j];
        const float* f = fmap + (((size_t)(b*C_IN + c) * HF + y0) * WF + x0);
        float v00 = f[0], v01 = f[1], v10 = f[WF], v11 = f[WF+1];
        float v = (1.f-wy)*((1.f-wx)*v00 + wx*v01) + wy*((1.f-wx)*v10 + wx*v11);
        g_roiT[((size_t)m*8 + (c>>4))*ROI_PER + (i+1)*324 + (j+1)*18 + (c&15)] = v;
    }
}

// ---------------------------------------------------------------------------
// K2: fused conv_s (+ReLU+GAP) and conv_c1 (+ReLU). FFMA2 over ci-pairs.
// CTA = (co_unit, m), 256 threads, 8 warps = 4 cg x 2 ph. Weights staged once,
// shared by both halves. grid (6, 64) -> 384 CTAs, 3/SM, single wave.
// ---------------------------------------------------------------------------
__global__ void __launch_bounds__(256, 3) k_conv(
    const float* __restrict__ b_s_all, const float* __restrict__ b_c1_all,
    const int* __restrict__ labels)
{
    int co_unit = blockIdx.x;
    int m  = blockIdx.y;
    int lab = labels[m];
    bool is_s = (co_unit < 4);
    int co0 = is_s ? co_unit*32 : (co_unit-4)*32;
    const float* bg = is_s ? (b_s_all + lab*C_IN + co0) : (b_c1_all + lab*64 + co0);

    __shared__ __align__(16) float w_sh [WT2];      // [k][cg][cp][o2]
    __shared__ __align__(16) float in_sh[ROI_PER];  // [row16][x18][ci18]
    __shared__ float red[32*56];

    int tid  = threadIdx.x;
    int wid  = tid >> 5;
    int cg   = wid >> 1;                 // 0..3 co group
    int ph   = wid & 1;                  // position half
    int lane = tid & 31;
    int row  = lane >> 2;                // 0..6 (lane<28)
    int x0q  = (lane & 3) * 4;
    bool act = lane < 28;

    ull acc[8][4];
    #pragma unroll
    for (int o = 0; o < 8; ++o)
        #pragma unroll
        for (int p = 0; p < 4; ++p) acc[o][p] = 0ull;

    const float* wsrc = g_wT + ((size_t)(lab*6 + co_unit)*8) * WT2;
    const float* isrc = g_roiT + ((size_t)m*8) * ROI_PER;

    for (int chunk = 0; chunk < 8; ++chunk) {
        __syncthreads();
        const float4* ws = (const float4*)(wsrc + chunk*WT2);
        #pragma unroll
        for (int t = 0; t < 5; ++t) {
            int idx = tid + t*256;
            if (idx < 1152) ((float4*)w_sh)[idx] = ws[idx];
        }
        const float4* is = (const float4*)(isrc + chunk*ROI_PER);
        #pragma unroll
        for (int t = 0; t < 6; ++t) {
            int idx = tid + t*256;
            if (idx < 1296) ((float4*)in_sh)[idx] = is[idx];
        }
        __syncthreads();

        if (act) {
            #pragma unroll 1
            for (int cp = 0; cp < 8; ++cp) {
                #pragma unroll
                for (int k = 0; k < 9; ++k) {
                    const int kr = k / 3, kc = k % 3;
                    const float* ibase =
                        &in_sh[(7*ph + row + kr)*324 + (x0q + kc)*18 + cp*2];
                    ull ip[4];
                    #pragma unroll
                    for (int p = 0; p < 4; ++p)
                        ip[p] = *(const ull*)&ibase[p*18];
                    const ulonglong2* wq =
                        (const ulonglong2*)&w_sh[((k*4 + cg)*8 + cp)*16];
                    #pragma unroll
                    for (int h = 0; h < 4; ++h) {
                        ulonglong2 wpair = wq[h];
                        #pragma unroll
                        for (int p = 0; p < 4; ++p)
                            ffma2(acc[2*h][p], wpair.x, ip[p]);
                        #pragma unroll
                        for (int p = 0; p < 4; ++p)
                            ffma2(acc[2*h+1][p], wpair.y, ip[p]);
                    }
                }
            }
        }
    }
    __syncthreads();

    if (is_s) {
        if (act) {
            #pragma unroll
            for (int o = 0; o < 8; ++o) {
                float bv = bg[cg*8 + o];
                float s = 0.f;
                #pragma unroll
                for (int p = 0; p < 4; ++p) {
                    float lo, hi; unpack2(acc[o][p], lo, hi);
                    if (x0q + p < 14) s += fmaxf(lo + hi + bv, 0.f);
                }
                red[(cg*8 + o)*56 + ph*28 + lane] = s;
            }
        }
        __syncthreads();
        if (tid < 32) {
            float s = 0.f;
            #pragma unroll
            for (int i = 0; i < 56; ++i) s += red[tid*56 + i];
            g_gap[m*C_IN + co0 + tid] = s;
        }
    } else if (act) {
        int gi = 7*ph + row;
        #pragma unroll
        for (int o = 0; o < 8; ++o) {
            float bv = bg[cg*8 + o];
            int co = co0 + cg*8 + o;
            #pragma unroll
            for (int p = 0; p < 4; ++p) {
                int x = x0q + p;
                if (x < 14) {
                    float lo, hi; unpack2(acc[o][p], lo, hi);
                    g_h1[((m*64 + co)*16 + gi + 1)*16 + (x + 1)] =
                        fmaxf(lo + hi + bv, 0.f);
                }
            }
        }
    }
}

// ---------------------------------------------------------------------------
// K3: conv_c2 partials (by<8) + FC head (by==8). grid (64,9), 256 threads.
// ---------------------------------------------------------------------------
__global__ void k_conv2fc(const float* __restrict__ w2_all,
                          const float* __restrict__ w_fc, const float* __restrict__ b_fc,
                          const int* __restrict__ labels, float* __restrict__ out)
{
    int m = blockIdx.x;
    int s = blockIdx.y;
    int lab = labels[m];
    int tid = threadIdx.x;

    if (s == 8) {                        // FC: one warp
        if (tid >= 32) return;
        int lane = tid;
        float4 ga = *(const float4*)&g_gap[m*128 + lane*4];
        float4 w0 = *(const float4*)&w_fc[(size_t)(lab*2    )*128 + lane*4];
        float4 w1 = *(const float4*)&w_fc[(size_t)(lab*2 + 1)*128 + lane*4];
        float g0 = ga.x * (1.0f/196.0f);
        float g1 = ga.y * (1.0f/196.0f);
        float g2 = ga.z * (1.0f/196.0f);
        float g3 = ga.w * (1.0f/196.0f);
        float s0 = g0*w0.x + g1*w0.y + g2*w0.z + g3*w0.w;
        float s1 = g0*w1.x + g1*w1.y + g2*w1.z + g3*w1.w;
        #pragma unroll
        for (int d = 16; d > 0; d >>= 1) {
            s0 += __shfl_xor_sync(0xffffffffu, s0, d);
            s1 += __shfl_xor_sync(0xffffffffu, s1, d);
        }
        if (lane == 0) {
            s0 += b_fc[lab*2 + 0];
            s1 += b_fc[lab*2 + 1];
            g_ss[m*2 + 0] = s0;
            g_ss[m*2 + 1] = s1;
            out[(size_t)2*SZ_IMG + m]      = s0;
            out[(size_t)2*SZ_IMG + 64 + m] = s1;
        }
        return;
    }

    __shared__ float h_sh[8*16*17];
    __shared__ float w2[72];

    for (int t = tid; t < 512; t += 256) {
        int ci = t / 64, rem4 = (t % 64) * 4;
        float4 v = *(const float4*)&g_h1[(size_t)(m*64 + s*8 + ci)*256 + rem4];
        int r = rem4 >> 4, x0 = rem4 & 15;
        #pragma unroll
        for (int q = 0; q < 4; ++q)
            h_sh[ci*272 + r*17 + x0 + q] = ((const float*)&v)[q];
    }
    if (tid < 72)
        w2[tid] = w2_all[(size_t)lab*576 + s*72 + tid];
    __syncthreads();

    if (tid < 196) {
        int i = tid / 14, j = tid % 14;
        float acc = 0.f;
        #pragma unroll
        for (int ci = 0; ci < 8; ++ci) {
            const float* hh = &h_sh[ci*272 + i*17 + j];
            const float* ww = &w2[ci*9];
            #pragma unroll
            for (int k = 0; k < 9; ++k)
                acc = fmaf(ww[k], hh[(k/3)*17 + (k%3)], acc);
        }
        g_cpart[(m*8 + s)*196 + tid] = acc;
    }
}

// ---------------------------------------------------------------------------
// K4: horizontal interp rows (+bias). grid 64, 256 threads.
// ---------------------------------------------------------------------------
__global__ void k_rowh(const float* __restrict__ b2_all, const int* __restrict__ labels)
{
    int m = blockIdx.x;
    __shared__ float c[196];
    __shared__ float bias;
    int tid = threadIdx.x;
    if (tid < 196) {
        float a = 0.f;
        #pragma unroll
        for (int s = 0; s < 8; ++s) a += g_cpart[(m*8 + s)*196 + tid];
        c[tid] = a;
    }
    if (tid == 224) bias = b2_all[labels[m]];
    __syncthreads();
    float b2v = bias;
    for (int t = tid; t < 14*640; t += 256) {
        int y = t / 640, X = t % 640;
        float ix = (X + 0.5f) * (14.0f/640.0f) - 0.5f;
        ix = fminf(fmaxf(ix, 0.f), 13.f);
        int x0 = (int)ix; if (x0 > 12) x0 = 12;
        float fx = ix - (float)x0;
        float v0 = c[y*14 + x0], v1 = c[y*14 + x0 + 1];
        g_rowh[(m*14 + y)*640 + X] = (1.f-fx)*v0 + fx*v1 + b2v;
    }
}

// ---------------------------------------------------------------------------
// K5: vertical interp + scale/shift. grid (240,64), 320 threads, 2 rows/block.
// ---------------------------------------------------------------------------
__global__ void k_resize(float* __restrict__ out)
{
    int m = blockIdx.y;
    int tid  = threadIdx.x;
    int half = tid / 160;
    int xq   = tid % 160;
    int Y = blockIdx.x*2 + half;

    float iy = (Y + 0.5f) * (14.0f/480.0f) - 0.5f;
    iy = fminf(fmaxf(iy, 0.f), 13.f);
    int y0 = (int)iy; if (y0 > 12) y0 = 12;
    float fy = iy - (float)y0;
    float gy = 1.f - fy;

    float scale = g_ss[m*2 + 0];
    float shift = g_ss[m*2 + 1];

    const float4* r0 = (const float4*)&g_rowh[(m*14 + y0)*640];
    const float4* r1 = (const float4*)&g_rowh[(m*14 + y0 + 1)*640];
    float4 t0 = r0[xq], t1 = r1[xq];

    float4 can, dep;
    can.x = gy*t0.x + fy*t1.x;
    can.y = gy*t0.y + fy*t1.y;
    can.z = gy*t0.z + fy*t1.z;
    can.w = gy*t0.w + fy*t1.w;
    dep.x = fmaxf(can.x*scale + shift, 0.001f);
    dep.y = fmaxf(can.y*scale + shift, 0.001f);
    dep.z = fmaxf(can.z*scale + shift, 0.001f);
    dep.w = fmaxf(can.w*scale + shift, 0.001f);

    size_t base = (size_t)m * H_OUT * W_OUT + (size_t)Y * W_OUT;
    ((float4*)(out + base))[xq] = dep;
    ((float4*)(out + SZ_IMG + base))[xq] = can;
}

// ---------------------------------------------------------------------------
extern "C" void kernel_launch(void* const* d_in, const int* in_sizes, int n_in,
                              void* d_out, int out_size)
{
    (void)in_sizes; (void)out_size;
    const float* fmap      = (const float*)d_in[2];
    const float* boxes     = (const float*)d_in[n_in-10];
    const int*   labels    = (const int*)  d_in[n_in-9];
    const float* w_conv_s  = (const float*)d_in[n_in-8];
    const float* b_conv_s  = (const float*)d_in[n_in-7];
    const float* w_fc      = (const float*)d_in[n_in-6];
    const float* b_fc      = (const float*)d_in[n_in-5];
    const float* w_conv_c1 = (const float*)d_in[n_in-4];
    const float* b_conv_c1 = (const float*)d_in[n_in-3];
    const float* w_conv_c2 = (const float*)d_in[n_in-2];
    const float* b_conv_c2 = (const float*)d_in[n_in-1];
    float* out = (float*)d_out;

    k_prep   <<<1136, 256>>>(w_conv_s, w_conv_c1, fmap, boxes);
    k_conv   <<<dim3(6, 64), 256>>>(b_conv_s, b_conv_c1, labels);
    k_conv2fc<<<dim3(64, 9), 256>>>(w_conv_c2, w_fc, b_fc, labels, out);
    k_rowh   <<<64, 256>>>(b_conv_c2, labels);
    k_resize <<<dim3(240, 64), 320>>>(out);
}

// round 7
// speedup vs baseline: 1.6754x; 1.6754x over previous
#include <cuda_runtime.h>

#define M_TOT 64
#define HF 120
#define WF 160
#define C_IN 128
#define H_OUT 480
#define W_OUT 640
#define SZ_IMG (M_TOT * H_OUT * W_OUT)   // 19,660,800
#define N_EXP 13
#define WT2 4608                         // 9k*4cg*8cp*8o*2 floats per (unit,chunk)
#define ROI_PER 5184                     // 16*324 floats per (m,chunk)

typedef unsigned long long ull;

// Scratch (zero-initialized at load; padded slots stay zero forever).
__device__ __align__(16) float g_wT  [N_EXP * 6 * 8 * WT2];   // [lab][unit][chunk][k][cg][cp][o2]
__device__ __align__(16) float g_roiT[M_TOT * 8 * ROI_PER];   // [m][chunk][row16][x18][ci16+2]
__device__ __align__(16) float g_h1  [M_TOT * 64 * 16 * 16];  // padded conv_c1 output
__device__ float g_gap2[M_TOT * 2 * C_IN];
__device__ float g_cpart[M_TOT * 8 * 196];
__device__ __align__(16) float g_rowh[M_TOT * 14 * 640];      // horiz-interp rows (+bias)
__device__ float g_ss  [M_TOT * 2];

__device__ __forceinline__ void unpack2(ull v, float& lo, float& hi) {
    asm("mov.b64 {%0, %1}, %2;" : "=f"(lo), "=f"(hi) : "l"(v));
}
__device__ __forceinline__ void ffma2(ull& d, ull a, ull b) {
    asm("fma.rn.f32x2 %0, %1, %2, %3;" : "=l"(d) : "l"(a), "l"(b), "l"(d));
}

// ---------------------------------------------------------------------------
// K1: fused weight transpose + ROI align. grid 1136: [0,624) wt, [624,1136) roi.
// ---------------------------------------------------------------------------
__global__ void k_prep(const float* __restrict__ w_s, const float* __restrict__ w_c1,
                       const float* __restrict__ fmap, const float* __restrict__ boxes)
{
    if (blockIdx.x < 624) {
        int id  = blockIdx.x;             // lab*48 + unit*8 + chunk
        int lab = id / 48, rem = id % 48;
        int unit = rem >> 3, chunk = rem & 7;
        const float* wb = (unit < 4)
            ? w_s  + ((size_t)lab*128 + unit*32)     * 1152
            : w_c1 + ((size_t)lab*64  + (unit-4)*32) * 1152;
        float* dst = g_wT + ((size_t)(lab*6 + unit)*8 + chunk) * WT2;
        for (int d = threadIdx.x; d < WT2; d += 256) {
            int k = d / 512, r2 = d % 512;
            int cg = r2 / 128, r3 = r2 % 128;
            int cp = r3 / 16, oe = r3 % 16;
            int o = oe >> 1, e = oe & 1;
            dst[d] = wb[(size_t)(cg*8 + o)*1152 + chunk*144 + (2*cp + e)*9 + k];
        }
        return;
    }

    int bi = blockIdx.x - 624;            // m*8 + seg
    int m = bi >> 3, seg = bi & 7;
    int b = m >> 4;
    __shared__ int   y0s[14], x0s[14];
    __shared__ float wys[14], wxs[14];

    float b0 = boxes[m*4+0], b1 = boxes[m*4+1], b2 = boxes[m*4+2], b3 = boxes[m*4+3];
    float y1 = 0.6f*b0, x1 = 0.6f*b1;
    float y2 = y1 + 0.1f + 0.3f*b2;
    float x2 = x1 + 0.1f + 0.3f*b3;

    int tid = threadIdx.x;
    if (tid < 14) {
        float t  = (tid + 0.5f) / 14.0f;
        float ys = (y1 + (y2 - y1) * t) * (float)(HF - 1);
        int y0 = (int)floorf(ys);
        if (y0 < 0) y0 = 0; if (y0 > HF-2) y0 = HF-2;
        y0s[tid] = y0;
        wys[tid] = fminf(fmaxf(ys - (float)y0, 0.f), 1.f);
    } else if (tid >= 32 && tid < 46) {
        int j = tid - 32;
        float t  = (j + 0.5f) / 14.0f;
        float xs = (x1 + (x2 - x1) * t) * (float)(WF - 1);
        int x0 = (int)floorf(xs);
        if (x0 < 0) x0 = 0; if (x0 > WF-2) x0 = WF-2;
        x0s[j] = x0;
        wxs[j] = fminf(fmaxf(xs - (float)x0, 0.f), 1.f);
    }
    __syncthreads();

    int base = seg * 16 * 196;
    for (int rel = tid; rel < 16 * 196; rel += 256) {
        int flat = base + rel;
        int c = flat / 196, r = flat % 196;
        int i = r / 14, j = r % 14;
        int y0 = y0s[i], x0 = x0s[j];
        float wy = wys[i], wx = wxs[j];
        const float* f = fmap + (((size_t)(b*C_IN + c) * HF + y0) * WF + x0);
        float v00 = f[0], v01 = f[1], v10 = f[WF], v11 = f[WF+1];
        float v = (1.f-wy)*((1.f-wx)*v00 + wx*v01) + wy*((1.f-wx)*v10 + wx*v11);
        g_roiT[((size_t)m*8 + (c>>4))*ROI_PER + (i+1)*324 + (j+1)*18 + (c&15)] = v;
    }
}

// ---------------------------------------------------------------------------
// K2: fused conv_s (+ReLU+GAP) and conv_c1 (+ReLU). FFMA2 over ci-pairs.
// Warp = co-group -> weight loads are LDS.128 broadcasts (crossbar-cheap).
// grid (12, 64): u = co_unit*2 + pos_half. 128 threads, lanes 0..27 active.
// (round-5 configuration: 128 thr, 4 CTAs/SM, 128 regs -> no spills)
// ---------------------------------------------------------------------------
__global__ void __launch_bounds__(128, 4) k_conv(
    const float* __restrict__ b_s_all, const float* __restrict__ b_c1_all,
    const int* __restrict__ labels)
{
    int u  = blockIdx.x;
    int m  = blockIdx.y;
    int lab = labels[m];
    int co_unit = u >> 1;
    int ph      = u & 1;
    bool is_s = (co_unit < 4);
    int co0 = is_s ? co_unit*32 : (co_unit-4)*32;
    const float* bg = is_s ? (b_s_all + lab*C_IN + co0) : (b_c1_all + lab*64 + co0);

    __shared__ __align__(16) float w_sh [WT2];      // [k][cg][cp][o2]
    __shared__ __align__(16) float in_sh[9*18*18];  // [(row*18+x)][ci18]
    __shared__ float red[32*28];

    int tid  = threadIdx.x;
    int cg   = tid >> 5;                 // warp id = co group
    int lane = tid & 31;
    int row  = lane >> 2;                // 0..6 (lane<28)
    int x0q  = (lane & 3) * 4;
    bool act = lane < 28;

    ull acc[8][4];
    #pragma unroll
    for (int o = 0; o < 8; ++o)
        #pragma unroll
        for (int p = 0; p < 4; ++p) acc[o][p] = 0ull;

    const float* wsrc = g_wT + ((size_t)(lab*6 + co_unit)*8) * WT2;
    const float* isrc = g_roiT + ((size_t)m*8) * ROI_PER + 2268*ph;  // 7*324*ph

    for (int chunk = 0; chunk < 8; ++chunk) {
        __syncthreads();
        const float4* ws = (const float4*)(wsrc + chunk*WT2);
        #pragma unroll
        for (int t = 0; t < 9; ++t)
            ((float4*)w_sh)[tid + t*128] = ws[tid + t*128];   // 1152 float4
        const float4* is = (const float4*)(isrc + chunk*ROI_PER);
        #pragma unroll
        for (int t = 0; t < 6; ++t) {
            int idx = tid + t*128;
            if (idx < 729) ((float4*)in_sh)[idx] = is[idx];
        }
        __syncthreads();

        if (act) {
            #pragma unroll 1
            for (int cp = 0; cp < 8; ++cp) {
                #pragma unroll
                for (int k = 0; k < 9; ++k) {
                    const int kr = k / 3, kc = k % 3;
                    const float* ibase = &in_sh[((row + kr)*18 + x0q + kc)*18 + cp*2];
                    ull ip[4];
                    #pragma unroll
                    for (int p = 0; p < 4; ++p)
                        ip[p] = *(const ull*)&ibase[p*18];
                    const ulonglong2* wq =
                        (const ulonglong2*)&w_sh[((k*4 + cg)*8 + cp)*16];
                    #pragma unroll
                    for (int h = 0; h < 4; ++h) {
                        ulonglong2 wpair = wq[h];
                        #pragma unroll
                        for (int p = 0; p < 4; ++p)
                            ffma2(acc[2*h][p], wpair.x, ip[p]);
                        #pragma unroll
                        for (int p = 0; p < 4; ++p)
                            ffma2(acc[2*h+1][p], wpair.y, ip[p]);
                    }
                }
            }
        }
    }
    __syncthreads();

    if (is_s) {
        if (act) {
            #pragma unroll
            for (int o = 0; o < 8; ++o) {
                float bv = bg[cg*8 + o];
                float s = 0.f;
                #pragma unroll
                for (int p = 0; p < 4; ++p) {
                    float lo, hi; unpack2(acc[o][p], lo, hi);
                    if (x0q + p < 14) s += fmaxf(lo + hi + bv, 0.f);
                }
                red[(cg*8 + o)*28 + row*4 + (lane & 3)] = s;
            }
        }
        __syncthreads();
        if (tid < 32) {
            float s = 0.f;
            #pragma unroll
            for (int i = 0; i < 28; ++i) s += red[tid*28 + i];
            g_gap2[(m*2 + ph)*C_IN + co0 + tid] = s;
        }
    } else if (act) {
        int gi = 7*ph + row;
        #pragma unroll
        for (int o = 0; o < 8; ++o) {
            float bv = bg[cg*8 + o];
            int co = co0 + cg*8 + o;
            #pragma unroll
            for (int p = 0; p < 4; ++p) {
                int x = x0q + p;
                if (x < 14) {
                    float lo, hi; unpack2(acc[o][p], lo, hi);
                    g_h1[((m*64 + co)*16 + gi + 1)*16 + (x + 1)] =
                        fmaxf(lo + hi + bv, 0.f);
                }
            }
        }
    }
}

// ---------------------------------------------------------------------------
// K3: conv_c2 partials (by<8) + FC head (by==8). grid (64,9), 256 threads.
// ---------------------------------------------------------------------------
__global__ void k_conv2fc(const float* __restrict__ w2_all,
                          const float* __restrict__ w_fc, const float* __restrict__ b_fc,
                          const int* __restrict__ labels, float* __restrict__ out)
{
    int m = blockIdx.x;
    int s = blockIdx.y;
    int lab = labels[m];
    int tid = threadIdx.x;

    if (s == 8) {                        // FC: one warp
        if (tid >= 32) return;
        int lane = tid;
        float4 ga = *(const float4*)&g_gap2[m*256 + lane*4];
        float4 gb = *(const float4*)&g_gap2[m*256 + 128 + lane*4];
        float4 w0 = *(const float4*)&w_fc[(size_t)(lab*2    )*128 + lane*4];
        float4 w1 = *(const float4*)&w_fc[(size_t)(lab*2 + 1)*128 + lane*4];
        float g0 = (ga.x + gb.x) * (1.0f/196.0f);
        float g1 = (ga.y + gb.y) * (1.0f/196.0f);
        float g2 = (ga.z + gb.z) * (1.0f/196.0f);
        float g3 = (ga.w + gb.w) * (1.0f/196.0f);
        float s0 = g0*w0.x + g1*w0.y + g2*w0.z + g3*w0.w;
        float s1 = g0*w1.x + g1*w1.y + g2*w1.z + g3*w1.w;
        #pragma unroll
        for (int d = 16; d > 0; d >>= 1) {
            s0 += __shfl_xor_sync(0xffffffffu, s0, d);
            s1 += __shfl_xor_sync(0xffffffffu, s1, d);
        }
        if (lane == 0) {
            s0 += b_fc[lab*2 + 0];
            s1 += b_fc[lab*2 + 1];
            g_ss[m*2 + 0] = s0;
            g_ss[m*2 + 1] = s1;
            out[(size_t)2*SZ_IMG + m]      = s0;
            out[(size_t)2*SZ_IMG + 64 + m] = s1;
        }
        return;
    }

    __shared__ float h_sh[8*16*17];
    __shared__ float w2[72];

    for (int t = tid; t < 512; t += 256) {
        int ci = t / 64, rem4 = (t % 64) * 4;
        float4 v = *(const float4*)&g_h1[(size_t)(m*64 + s*8 + ci)*256 + rem4];
        int r = rem4 >> 4, x0 = rem4 & 15;
        #pragma unroll
        for (int q = 0; q < 4; ++q)
            h_sh[ci*272 + r*17 + x0 + q] = ((const float*)&v)[q];
    }
    if (tid < 72)
        w2[tid] = w2_all[(size_t)lab*576 + s*72 + tid];
    __syncthreads();

    if (tid < 196) {
        int i = tid / 14, j = tid % 14;
        float acc = 0.f;
        #pragma unroll
        for (int ci = 0; ci < 8; ++ci) {
            const float* hh = &h_sh[ci*272 + i*17 + j];
            const float* ww = &w2[ci*9];
            #pragma unroll
            for (int k = 0; k < 9; ++k)
                acc = fmaf(ww[k], hh[(k/3)*17 + (k%3)], acc);
        }
        g_cpart[(m*8 + s)*196 + tid] = acc;
    }
}

// ---------------------------------------------------------------------------
// K4: horizontal interp rows (+bias). grid 64, 256 threads.
// ---------------------------------------------------------------------------
__global__ void k_rowh(const float* __restrict__ b2_all, const int* __restrict__ labels)
{
    int m = blockIdx.x;
    __shared__ float c[196];
    __shared__ float bias;
    int tid = threadIdx.x;
    if (tid < 196) {
        float a = 0.f;
        #pragma unroll
        for (int s = 0; s < 8; ++s) a += g_cpart[(m*8 + s)*196 + tid];
        c[tid] = a;
    }
    if (tid == 224) bias = b2_all[labels[m]];
    __syncthreads();
    float b2v = bias;
    for (int t = tid; t < 14*640; t += 256) {
        int y = t / 640, X = t % 640;
        float ix = (X + 0.5f) * (14.0f/640.0f) - 0.5f;
        ix = fminf(fmaxf(ix, 0.f), 13.f);
        int x0 = (int)ix; if (x0 > 12) x0 = 12;
        float fx = ix - (float)x0;
        float v0 = c[y*14 + x0], v1 = c[y*14 + x0 + 1];
        g_rowh[(m*14 + y)*640 + X] = (1.f-fx)*v0 + fx*v1 + b2v;
    }
}

// ---------------------------------------------------------------------------
// K5: vertical interp + scale/shift. grid (240,64), 320 threads, 2 rows/block.
// ---------------------------------------------------------------------------
__global__ void k_resize(float* __restrict__ out)
{
    int m = blockIdx.y;
    int tid  = threadIdx.x;
    int half = tid / 160;
    int xq   = tid % 160;
    int Y = blockIdx.x*2 + half;

    float iy = (Y + 0.5f) * (14.0f/480.0f) - 0.5f;
    iy = fminf(fmaxf(iy, 0.f), 13.f);
    int y0 = (int)iy; if (y0 > 12) y0 = 12;
    float fy = iy - (float)y0;
    float gy = 1.f - fy;

    float scale = g_ss[m*2 + 0];
    float shift = g_ss[m*2 + 1];

    const float4* r0 = (const float4*)&g_rowh[(m*14 + y0)*640];
    const float4* r1 = (const float4*)&g_rowh[(m*14 + y0 + 1)*640];
    float4 t0 = r0[xq], t1 = r1[xq];

    float4 can, dep;
    can.x = gy*t0.x + fy*t1.x;
    can.y = gy*t0.y + fy*t1.y;
    can.z = gy*t0.z + fy*t1.z;
    can.w = gy*t0.w + fy*t1.w;
    dep.x = fmaxf(can.x*scale + shift, 0.001f);
    dep.y = fmaxf(can.y*scale + shift, 0.001f);
    dep.z = fmaxf(can.z*scale + shift, 0.001f);
    dep.w = fmaxf(can.w*scale + shift, 0.001f);

    size_t base = (size_t)m * H_OUT * W_OUT + (size_t)Y * W_OUT;
    ((float4*)(out + base))[xq] = dep;
    ((float4*)(out + SZ_IMG + base))[xq] = can;
}

// ---------------------------------------------------------------------------
extern "C" void kernel_launch(void* const* d_in, const int* in_sizes, int n_in,
                              void* d_out, int out_size)
{
    (void)in_sizes; (void)out_size;
    const float* fmap      = (const float*)d_in[2];
    const float* boxes     = (const float*)d_in[n_in-10];
    const int*   labels    = (const int*)  d_in[n_in-9];
    const float* w_conv_s  = (const float*)d_in[n_in-8];
    const float* b_conv_s  = (const float*)d_in[n_in-7];
    const float* w_fc      = (const float*)d_in[n_in-6];
    const float* b_fc      = (const float*)d_in[n_in-5];
    const float* w_conv_c1 = (const float*)d_in[n_in-4];
    const float* b_conv_c1 = (const float*)d_in[n_in-3];
    const float* w_conv_c2 = (const float*)d_in[n_in-2];
    const float* b_conv_c2 = (const float*)d_in[n_in-1];
    float* out = (float*)d_out;

    k_prep   <<<1136, 256>>>(w_conv_s, w_conv_c1, fmap, boxes);
    k_conv   <<<dim3(12, 64), 128>>>(b_conv_s, b_conv_c1, labels);
    k_conv2fc<<<dim3(64, 9), 256>>>(w_conv_c2, w_fc, b_fc, labels, out);
    k_rowh   <<<64, 256>>>(b_conv_c2, labels);
    k_resize <<<dim3(240, 64), 320>>>(out);
}